// round 1
// baseline (speedup 1.0000x reference)
#include <cuda_runtime.h>
#include <cstddef>

#define EB   2048        // embed dim
#define SB   2048        // seq len
#define BB   2           // batch
#define HH   16          // heads
#define DH   128         // head dim
#define MTOT (BB*SB)     // 4096 rows

// ---------------- scratch (device globals; no allocation) ----------------
__device__ float g_Q[(size_t)MTOT * EB];
__device__ float g_K[(size_t)MTOT * EB];
__device__ float g_V[(size_t)MTOT * EB];
__device__ float g_C[(size_t)MTOT * EB];

// =========================================================================
// GEMM:  C[M,N] = A[M,K] @ W[N,K]^T + bias[N]      (torch Linear semantics)
// Tiles: 128x128x16, 256 threads, 8x8 per thread, float4 vectorized smem.
// =========================================================================
#define GBM 128
#define GBN 128
#define GBK 16
#define GPITCH (GBM + 4)

__global__ __launch_bounds__(256, 2)
void gemm_bias_kernel(const float* __restrict__ A,
                      const float* __restrict__ W,
                      const float* __restrict__ bias,
                      float* __restrict__ C,
                      int M, int N, int K)
{
    __shared__ __align__(16) float As[GBK][GPITCH];
    __shared__ __align__(16) float Ws[GBK][GPITCH];

    const int tid = threadIdx.x;
    const int tx  = tid & 15;         // 0..15 -> N direction
    const int ty  = tid >> 4;         // 0..15 -> M direction
    const int row0 = blockIdx.y * GBM;
    const int col0 = blockIdx.x * GBN;

    float acc[8][8];
#pragma unroll
    for (int i = 0; i < 8; i++)
#pragma unroll
        for (int j = 0; j < 8; j++) acc[i][j] = 0.f;

    for (int k0 = 0; k0 < K; k0 += GBK) {
        // load 128x16 tiles of A and W (each thread: 2 float4 of each)
#pragma unroll
        for (int it = 0; it < 2; it++) {
            int lane = tid + it * 256;     // 0..511
            int m    = lane >> 2;          // 0..127
            int k4   = (lane & 3) * 4;     // 0,4,8,12
            float4 va = *reinterpret_cast<const float4*>(
                &A[(size_t)(row0 + m) * K + k0 + k4]);
            As[k4 + 0][m] = va.x; As[k4 + 1][m] = va.y;
            As[k4 + 2][m] = va.z; As[k4 + 3][m] = va.w;
            float4 vw = *reinterpret_cast<const float4*>(
                &W[(size_t)(col0 + m) * K + k0 + k4]);
            Ws[k4 + 0][m] = vw.x; Ws[k4 + 1][m] = vw.y;
            Ws[k4 + 2][m] = vw.z; Ws[k4 + 3][m] = vw.w;
        }
        __syncthreads();

#pragma unroll
        for (int k = 0; k < GBK; k++) {
            float4 a0 = *reinterpret_cast<const float4*>(&As[k][ty * 8]);
            float4 a1 = *reinterpret_cast<const float4*>(&As[k][ty * 8 + 4]);
            float4 b0 = *reinterpret_cast<const float4*>(&Ws[k][tx * 8]);
            float4 b1 = *reinterpret_cast<const float4*>(&Ws[k][tx * 8 + 4]);
            float a[8] = {a0.x, a0.y, a0.z, a0.w, a1.x, a1.y, a1.z, a1.w};
            float b[8] = {b0.x, b0.y, b0.z, b0.w, b1.x, b1.y, b1.z, b1.w};
#pragma unroll
            for (int i = 0; i < 8; i++)
#pragma unroll
                for (int j = 0; j < 8; j++)
                    acc[i][j] = fmaf(a[i], b[j], acc[i][j]);
        }
        __syncthreads();
    }

#pragma unroll
    for (int i = 0; i < 8; i++) {
        int r = row0 + ty * 8 + i;
#pragma unroll
        for (int j = 0; j < 8; j += 4) {
            int c = col0 + tx * 8 + j;
            float4 o;
            o.x = acc[i][j + 0] + bias[c + 0];
            o.y = acc[i][j + 1] + bias[c + 1];
            o.z = acc[i][j + 2] + bias[c + 2];
            o.w = acc[i][j + 3] + bias[c + 3];
            *reinterpret_cast<float4*>(&C[(size_t)r * N + c]) = o;
        }
    }
}

// =========================================================================
// Flash attention (causal), fp32. One block per (q-tile of 64, b*h).
// Q/K/V in [B,S,H*D] layout. Output to g_C in same layout.
// =========================================================================
#define BQ 64
#define BKV 64
#define APITCH 132
#define PPITCH 68

// smem floats: Q(64*132) + K(64*132) + V(64*132) + P(64*68)
#define ATTN_SMEM_FLOATS (3 * BQ * APITCH + BQ * PPITCH)
#define ATTN_SMEM_BYTES  (ATTN_SMEM_FLOATS * 4)

__global__ __launch_bounds__(256, 1)
void attn_kernel()
{
    extern __shared__ __align__(16) float smem[];
    float (*Qs)[APITCH] = reinterpret_cast<float (*)[APITCH]>(smem);
    float (*Ks)[APITCH] = reinterpret_cast<float (*)[APITCH]>(smem + BQ * APITCH);
    float (*Vs)[APITCH] = reinterpret_cast<float (*)[APITCH]>(smem + 2 * BQ * APITCH);
    float (*Ps)[PPITCH] = reinterpret_cast<float (*)[PPITCH]>(smem + 3 * BQ * APITCH);

    const int tid = threadIdx.x;
    const int tx  = tid & 15;
    const int ty  = tid >> 4;
    const int qt  = blockIdx.x;          // 0..31
    const int b   = blockIdx.y >> 4;
    const int h   = blockIdx.y & 15;
    const int q0  = qt * BQ;
    const float scale = 0.08838834764831845f;  // 1/sqrt(128)

    const float* Qg = g_Q + (size_t)b * SB * EB + (size_t)h * DH;
    const float* Kg = g_K + (size_t)b * SB * EB + (size_t)h * DH;
    const float* Vg = g_V + (size_t)b * SB * EB + (size_t)h * DH;

    // load Q tile: 64 x 128 floats = 2048 float4, 8 per thread
#pragma unroll
    for (int it = 0; it < 8; it++) {
        int lane = tid + it * 256;
        int r = lane >> 5;            // 0..63
        int c = (lane & 31) * 4;      // 0..124
        *reinterpret_cast<float4*>(&Qs[r][c]) =
            *reinterpret_cast<const float4*>(&Qg[(size_t)(q0 + r) * EB + c]);
    }

    const int r0 = ty * 4;    // 4 query rows owned
    const int c0 = tx * 4;    // 4 score cols owned
    const int d0 = tx * 8;    // 8 output dims owned

    float m_i[4], l_i[4], acc[4][8];
#pragma unroll
    for (int i = 0; i < 4; i++) {
        m_i[i] = -1e30f; l_i[i] = 0.f;
#pragma unroll
        for (int j = 0; j < 8; j++) acc[i][j] = 0.f;
    }

    for (int kt = 0; kt <= qt; kt++) {
        const int k0g = kt * BKV;
        __syncthreads();   // protect K/V smem reuse (and first-iter Q load)

        // load K and V tiles
#pragma unroll
        for (int it = 0; it < 8; it++) {
            int lane = tid + it * 256;
            int r = lane >> 5;
            int c = (lane & 31) * 4;
            *reinterpret_cast<float4*>(&Ks[r][c]) =
                *reinterpret_cast<const float4*>(&Kg[(size_t)(k0g + r) * EB + c]);
            *reinterpret_cast<float4*>(&Vs[r][c]) =
                *reinterpret_cast<const float4*>(&Vg[(size_t)(k0g + r) * EB + c]);
        }
        __syncthreads();

        // ---- S = Q K^T (4x4 micro-tile per thread), vectorized over d ----
        float s[4][4];
#pragma unroll
        for (int i = 0; i < 4; i++)
#pragma unroll
            for (int j = 0; j < 4; j++) s[i][j] = 0.f;

#pragma unroll 8
        for (int d = 0; d < DH; d += 4) {
            float4 qv[4];
#pragma unroll
            for (int i = 0; i < 4; i++)
                qv[i] = *reinterpret_cast<const float4*>(&Qs[r0 + i][d]);
#pragma unroll
            for (int j = 0; j < 4; j++) {
                float4 kv = *reinterpret_cast<const float4*>(&Ks[c0 + j][d]);
#pragma unroll
                for (int i = 0; i < 4; i++) {
                    s[i][j] = fmaf(qv[i].x, kv.x, s[i][j]);
                    s[i][j] = fmaf(qv[i].y, kv.y, s[i][j]);
                    s[i][j] = fmaf(qv[i].z, kv.z, s[i][j]);
                    s[i][j] = fmaf(qv[i].w, kv.w, s[i][j]);
                }
            }
        }

        // scale + causal mask (only the diagonal tile needs masking)
        const bool diag = (kt == qt);
#pragma unroll
        for (int i = 0; i < 4; i++)
#pragma unroll
            for (int j = 0; j < 4; j++) {
                float v = s[i][j] * scale;
                if (diag && (k0g + c0 + j) > (q0 + r0 + i)) v = -1e30f;
                s[i][j] = v;
            }

        // ---- online softmax ----
        float rmax[4];
#pragma unroll
        for (int i = 0; i < 4; i++)
            rmax[i] = fmaxf(fmaxf(s[i][0], s[i][1]), fmaxf(s[i][2], s[i][3]));
#pragma unroll
        for (int off = 8; off >= 1; off >>= 1)
#pragma unroll
            for (int i = 0; i < 4; i++)
                rmax[i] = fmaxf(rmax[i], __shfl_xor_sync(0xffffffffu, rmax[i], off, 16));

        float alpha[4], rsum[4];
#pragma unroll
        for (int i = 0; i < 4; i++) {
            float m_new = fmaxf(m_i[i], rmax[i]);
            alpha[i] = __expf(m_i[i] - m_new);
            m_i[i] = m_new;
            float rs = 0.f;
#pragma unroll
            for (int j = 0; j < 4; j++) {
                float p = __expf(s[i][j] - m_new);
                s[i][j] = p;
                rs += p;
            }
            rsum[i] = rs;
        }
#pragma unroll
        for (int off = 8; off >= 1; off >>= 1)
#pragma unroll
            for (int i = 0; i < 4; i++)
                rsum[i] += __shfl_xor_sync(0xffffffffu, rsum[i], off, 16);

#pragma unroll
        for (int i = 0; i < 4; i++) {
            l_i[i] = l_i[i] * alpha[i] + rsum[i];
            *reinterpret_cast<float4*>(&Ps[r0 + i][c0]) =
                make_float4(s[i][0], s[i][1], s[i][2], s[i][3]);
#pragma unroll
            for (int j = 0; j < 8; j++) acc[i][j] *= alpha[i];
        }
        __syncthreads();

        // ---- acc += P @ V ----
#pragma unroll 4
        for (int k = 0; k < BKV; k++) {
            float4 v0 = *reinterpret_cast<const float4*>(&Vs[k][d0]);
            float4 v1 = *reinterpret_cast<const float4*>(&Vs[k][d0 + 4]);
#pragma unroll
            for (int i = 0; i < 4; i++) {
                float p = Ps[r0 + i][k];
                acc[i][0] = fmaf(p, v0.x, acc[i][0]);
                acc[i][1] = fmaf(p, v0.y, acc[i][1]);
                acc[i][2] = fmaf(p, v0.z, acc[i][2]);
                acc[i][3] = fmaf(p, v0.w, acc[i][3]);
                acc[i][4] = fmaf(p, v1.x, acc[i][4]);
                acc[i][5] = fmaf(p, v1.y, acc[i][5]);
                acc[i][6] = fmaf(p, v1.z, acc[i][6]);
                acc[i][7] = fmaf(p, v1.w, acc[i][7]);
            }
        }
    }

    // ---- normalize + write ctx in [B,S,H*D] ----
#pragma unroll
    for (int i = 0; i < 4; i++) {
        float inv = 1.f / l_i[i];
        size_t base = ((size_t)b * SB + q0 + r0 + i) * EB + (size_t)h * DH + d0;
        float4 o0, o1;
        o0.x = acc[i][0] * inv; o0.y = acc[i][1] * inv;
        o0.z = acc[i][2] * inv; o0.w = acc[i][3] * inv;
        o1.x = acc[i][4] * inv; o1.y = acc[i][5] * inv;
        o1.z = acc[i][6] * inv; o1.w = acc[i][7] * inv;
        *reinterpret_cast<float4*>(&g_C[base])     = o0;
        *reinterpret_cast<float4*>(&g_C[base + 4]) = o1;
    }
}

// =========================================================================
extern "C" void kernel_launch(void* const* d_in, const int* in_sizes, int n_in,
                              void* d_out, int out_size)
{
    const float* x  = (const float*)d_in[0];
    const float* Wq = (const float*)d_in[1];
    const float* bq = (const float*)d_in[2];
    const float* Wk = (const float*)d_in[3];
    const float* bk = (const float*)d_in[4];
    const float* Wv = (const float*)d_in[5];
    const float* bv = (const float*)d_in[6];
    const float* Wo = (const float*)d_in[7];
    const float* bo = (const float*)d_in[8];
    float* out = (float*)d_out;

    float *Qp, *Kp, *Vp, *Cp;
    cudaGetSymbolAddress((void**)&Qp, g_Q);
    cudaGetSymbolAddress((void**)&Kp, g_K);
    cudaGetSymbolAddress((void**)&Vp, g_V);
    cudaGetSymbolAddress((void**)&Cp, g_C);

    cudaFuncSetAttribute(attn_kernel,
                         cudaFuncAttributeMaxDynamicSharedMemorySize,
                         ATTN_SMEM_BYTES);

    dim3 ggrid(EB / GBN, MTOT / GBM);   // (16, 32)
    gemm_bias_kernel<<<ggrid, 256>>>(x, Wq, bq, Qp, MTOT, EB, EB);
    gemm_bias_kernel<<<ggrid, 256>>>(x, Wk, bk, Kp, MTOT, EB, EB);
    gemm_bias_kernel<<<ggrid, 256>>>(x, Wv, bv, Vp, MTOT, EB, EB);

    attn_kernel<<<dim3(SB / BQ, BB * HH), 256, ATTN_SMEM_BYTES>>>();

    gemm_bias_kernel<<<ggrid, 256>>>(Cp, Wo, bo, out, MTOT, EB, EB);
}

// round 3
// speedup vs baseline: 3.0543x; 3.0543x over previous
#include <cuda_runtime.h>
#include <cuda_bf16.h>
#include <cstdint>
#include <cstddef>

#define EB 2048
#define SB 2048
#define BB 2
#define HH 16
#define DH 128
#define MTOT (BB*SB)

// ---------------- scratch (device globals; no allocation) ----------------
__device__ __nv_bfloat16 g_xh[(size_t)MTOT * EB];
__device__ __nv_bfloat16 g_xl[(size_t)MTOT * EB];
__device__ __nv_bfloat16 g_wh[(size_t)4 * EB * EB];
__device__ __nv_bfloat16 g_wl[(size_t)4 * EB * EB];
__device__ __nv_bfloat16 g_qh[(size_t)MTOT * EB];
__device__ __nv_bfloat16 g_ql[(size_t)MTOT * EB];
__device__ __nv_bfloat16 g_kh[(size_t)MTOT * EB];
__device__ __nv_bfloat16 g_kl[(size_t)MTOT * EB];
__device__ __nv_bfloat16 g_vh[(size_t)MTOT * EB];
__device__ __nv_bfloat16 g_vl[(size_t)MTOT * EB];
__device__ __nv_bfloat16 g_ch[(size_t)MTOT * EB];
__device__ __nv_bfloat16 g_cl[(size_t)MTOT * EB];

// ---------------- helpers ----------------
__device__ __forceinline__ uint32_t smem_u32(const void* p) {
    uint32_t a;
    asm("{ .reg .u64 t; cvta.to.shared.u64 t, %1; cvt.u32.u64 %0, t; }"
        : "=r"(a) : "l"(p));
    return a;
}

__device__ __forceinline__ void ldsm4(uint32_t* r, uint32_t a) {
    asm volatile("ldmatrix.sync.aligned.m8n8.x4.shared.b16 {%0,%1,%2,%3}, [%4];"
                 : "=r"(r[0]), "=r"(r[1]), "=r"(r[2]), "=r"(r[3]) : "r"(a));
}
__device__ __forceinline__ void ldsm4t(uint32_t* r, uint32_t a) {
    asm volatile("ldmatrix.sync.aligned.m8n8.x4.trans.shared.b16 {%0,%1,%2,%3}, [%4];"
                 : "=r"(r[0]), "=r"(r[1]), "=r"(r[2]), "=r"(r[3]) : "r"(a));
}

__device__ __forceinline__ void mma16816(float* d, const uint32_t* a, const uint32_t* b) {
    asm volatile(
        "mma.sync.aligned.m16n8k16.row.col.f32.bf16.bf16.f32 "
        "{%0,%1,%2,%3}, {%4,%5,%6,%7}, {%8,%9}, {%0,%1,%2,%3};"
        : "+f"(d[0]), "+f"(d[1]), "+f"(d[2]), "+f"(d[3])
        : "r"(a[0]), "r"(a[1]), "r"(a[2]), "r"(a[3]), "r"(b[0]), "r"(b[1]));
}

__device__ __forceinline__ void cp16(uint32_t dst, const void* src) {
    asm volatile("cp.async.cg.shared.global [%0], [%1], 16;" :: "r"(dst), "l"(src));
}
#define CP_COMMIT() asm volatile("cp.async.commit_group;" ::: "memory")
#define CP_WAIT1()  asm volatile("cp.async.wait_group 1;" ::: "memory")

__device__ __forceinline__ uint32_t pack_bf(float lo, float hi) {
    __nv_bfloat162 t = __float22bfloat162_rn(make_float2(lo, hi));
    return *reinterpret_cast<uint32_t*>(&t);
}
__device__ __forceinline__ float bf_round(float v) {
    return __bfloat162float(__float2bfloat16_rn(v));
}

// =========================================================================
// fp32 -> bf16 hi/lo split
// =========================================================================
__global__ void conv_split_kernel(const float* __restrict__ in,
                                  __nv_bfloat16* __restrict__ hi,
                                  __nv_bfloat16* __restrict__ lo, int n4)
{
    int i = blockIdx.x * blockDim.x + threadIdx.x;
    if (i >= n4) return;
    float4 v = reinterpret_cast<const float4*>(in)[i];
    float h0 = bf_round(v.x), h1 = bf_round(v.y), h2 = bf_round(v.z), h3 = bf_round(v.w);
    uint2 H, L;
    H.x = pack_bf(v.x, v.y); H.y = pack_bf(v.z, v.w);
    L.x = pack_bf(v.x - h0, v.y - h1); L.y = pack_bf(v.z - h2, v.w - h3);
    reinterpret_cast<uint2*>(hi)[i] = H;
    reinterpret_cast<uint2*>(lo)[i] = L;
}

// =========================================================================
// HMMA GEMM: C[M,N] = (Ah+Al)[M,K] @ (Bh+Bl)[N,K]^T + bias[N]
// 3-term split.  CTA 128x128, kc=32, 8 warps (2x4), warp tile 64x32.
// Output: fp32 (Cf) or split-bf16 pair (Ch, Cl).
// =========================================================================
#define TM 128
#define TN 128
#define KC 32
#define GP 80                     // bytes/row in smem (64B data + 16B pad)
#define TILEB (128 * GP)          // 10240
#define STAGEB (4 * TILEB)        // 40960
#define GEMM_SMEM (2 * STAGEB)    // 81920

__device__ __forceinline__ void gemm_issue(
    const __nv_bfloat16* s0, const __nv_bfloat16* s1,
    const __nv_bfloat16* s2, const __nv_bfloat16* s3,
    int K, int k0, uint32_t base, int tid)
{
#pragma unroll
    for (int j = 0; j < 8; j++) {
        const int tile = j >> 1;
        const int part = (j & 1) * 256 + tid;   // 0..511
        const int r = part >> 2;
        const int c = part & 3;
        const __nv_bfloat16* g =
            (tile == 0 ? s0 : tile == 1 ? s1 : tile == 2 ? s2 : s3)
            + (size_t)r * K + k0 + c * 8;
        cp16(base + tile * TILEB + r * GP + c * 16, g);
    }
}

__global__ __launch_bounds__(256, 1)
void gemm_tc(const __nv_bfloat16* __restrict__ Ah, const __nv_bfloat16* __restrict__ Al,
             const __nv_bfloat16* __restrict__ Bh, const __nv_bfloat16* __restrict__ Bl,
             const float* __restrict__ bias,
             float* __restrict__ Cf,
             __nv_bfloat16* __restrict__ Ch, __nv_bfloat16* __restrict__ Cl,
             int M, int N, int K)
{
    extern __shared__ __align__(128) char smem[];
    const uint32_t sb = smem_u32(smem);
    const int tid = threadIdx.x, lane = tid & 31, wid = tid >> 5;
    const int wm = wid >> 2, wn = wid & 3;
    const int m0 = blockIdx.y * TM, n0 = blockIdx.x * TN;

    const __nv_bfloat16* s0 = Ah + (size_t)m0 * K;
    const __nv_bfloat16* s1 = Al + (size_t)m0 * K;
    const __nv_bfloat16* s2 = Bh + (size_t)n0 * K;
    const __nv_bfloat16* s3 = Bl + (size_t)n0 * K;

    gemm_issue(s0, s1, s2, s3, K, 0, sb, tid);            CP_COMMIT();
    gemm_issue(s0, s1, s2, s3, K, KC, sb + STAGEB, tid);  CP_COMMIT();

    float acc[4][4][4];
#pragma unroll
    for (int a = 0; a < 4; a++)
#pragma unroll
        for (int b = 0; b < 4; b++)
#pragma unroll
            for (int c = 0; c < 4; c++) acc[a][b][c] = 0.f;

    const int arow = wm * 64 + (lane & 15);
    const uint32_t ak8 = ((lane >> 4) << 3) * 2;
    const int brow = wn * 32 + ((lane >> 4) << 3) + (lane & 7);
    const uint32_t bk8 = (((lane >> 3) & 1) << 3) * 2;

    const int niter = K / KC;   // 64
    for (int it = 0; it < niter; ++it) {
        CP_WAIT1();
        __syncthreads();
        const uint32_t st = sb + (it & 1) * STAGEB;
        const uint32_t a_h = st, a_l = st + TILEB, b_h = st + 2 * TILEB, b_l = st + 3 * TILEB;
#pragma unroll
        for (int ks = 0; ks < 2; ++ks) {
            uint32_t ah[4][4], al[4][4];
            const uint32_t ao = ak8 + ks * 32;
#pragma unroll
            for (int mt = 0; mt < 4; mt++) {
                uint32_t ra = (uint32_t)(arow + mt * 16) * GP + ao;
                ldsm4(ah[mt], a_h + ra);
                ldsm4(al[mt], a_l + ra);
            }
#pragma unroll
            for (int np = 0; np < 2; np++) {
                uint32_t bh[4], bl[4];
                uint32_t rb = (uint32_t)(brow + np * 16) * GP + bk8 + ks * 32;
                ldsm4(bh, b_h + rb);
                ldsm4(bl, b_l + rb);
#pragma unroll
                for (int mt = 0; mt < 4; mt++) {
                    mma16816(acc[mt][2 * np],     ah[mt], bh);
                    mma16816(acc[mt][2 * np],     ah[mt], bl);
                    mma16816(acc[mt][2 * np],     al[mt], bh);
                    mma16816(acc[mt][2 * np + 1], ah[mt], bh + 2);
                    mma16816(acc[mt][2 * np + 1], ah[mt], bl + 2);
                    mma16816(acc[mt][2 * np + 1], al[mt], bh + 2);
                }
            }
        }
        __syncthreads();
        if (it + 2 < niter)
            gemm_issue(s0, s1, s2, s3, K, (it + 2) * KC, sb + (it & 1) * STAGEB, tid);
        CP_COMMIT();
    }

    // epilogue
    const int g = lane >> 2, q = lane & 3;
#pragma unroll
    for (int mt = 0; mt < 4; mt++) {
        const int r0 = m0 + wm * 64 + mt * 16 + g;
        const int r1 = r0 + 8;
#pragma unroll
        for (int nt = 0; nt < 4; nt++) {
            const int c = n0 + wn * 32 + nt * 8 + q * 2;
            const float b0 = __ldg(bias + c), b1 = __ldg(bias + c + 1);
            const float v00 = acc[mt][nt][0] + b0, v01 = acc[mt][nt][1] + b1;
            const float v10 = acc[mt][nt][2] + b0, v11 = acc[mt][nt][3] + b1;
            if (Cf) {
                *reinterpret_cast<float2*>(Cf + (size_t)r0 * N + c) = make_float2(v00, v01);
                *reinterpret_cast<float2*>(Cf + (size_t)r1 * N + c) = make_float2(v10, v11);
            } else {
                const float h00 = bf_round(v00), h01 = bf_round(v01);
                const float h10 = bf_round(v10), h11 = bf_round(v11);
                *reinterpret_cast<uint32_t*>(Ch + (size_t)r0 * N + c) = pack_bf(v00, v01);
                *reinterpret_cast<uint32_t*>(Cl + (size_t)r0 * N + c) = pack_bf(v00 - h00, v01 - h01);
                *reinterpret_cast<uint32_t*>(Ch + (size_t)r1 * N + c) = pack_bf(v10, v11);
                *reinterpret_cast<uint32_t*>(Cl + (size_t)r1 * N + c) = pack_bf(v10 - h10, v11 - h11);
            }
        }
    }
}

// =========================================================================
// Flash attention (causal) with HMMA, split-bf16 throughout.
// CTA: 128 q-rows x (b,h). 8 warps, warp owns 16 rows. KV tiles of 64.
// =========================================================================
#define AQ 128
#define AKV 64
#define AP 272                      // bytes/row (256B data + 16B pad)
#define QSZ (128 * AP)              // 34816
#define KSZ (64 * AP)               // 17408
#define ATTN_SMEM (2 * QSZ + 4 * KSZ)   // 139264

__global__ __launch_bounds__(256, 1)
void attn_tc()
{
    extern __shared__ __align__(128) char smem[];
    const uint32_t sb = smem_u32(smem);
    const uint32_t QH = sb, QL = sb + QSZ, KVB = sb + 2 * QSZ;
    const int tid = threadIdx.x, lane = tid & 31, w = tid >> 5;
    const int qt = gridDim.x - 1 - blockIdx.x;      // big tiles first
    const int b  = blockIdx.y >> 4, h = blockIdx.y & 15;
    const int q0 = qt * AQ;
    const float scale = 0.08838834764831845f;       // 1/sqrt(128)

    const size_t hoff = (size_t)h * DH;
    const size_t bbase = (size_t)b * SB * EB + hoff;
    const __nv_bfloat16* qhg = g_qh + bbase + (size_t)q0 * EB;
    const __nv_bfloat16* qlg = g_ql + bbase + (size_t)q0 * EB;
    const __nv_bfloat16* khg = g_kh + bbase;
    const __nv_bfloat16* klg = g_kl + bbase;
    const __nv_bfloat16* vhg = g_vh + bbase;
    const __nv_bfloat16* vlg = g_vl + bbase;

    // load Q (128 x 128 bf16, hi+lo)
#pragma unroll
    for (int j = 0; j < 16; j++) {
        const int arr = j >> 3;
        const int part = (j & 7) * 256 + tid;   // 0..2047
        const int r = part >> 4;
        const int c = part & 15;
        const __nv_bfloat16* g = (arr ? qlg : qhg) + (size_t)r * EB + c * 8;
        uint4 v = *reinterpret_cast<const uint4*>(g);
        *reinterpret_cast<uint4*>(smem + arr * QSZ + r * AP + c * 16) = v;
    }

    float o[16][4];
#pragma unroll
    for (int i = 0; i < 16; i++)
#pragma unroll
        for (int j = 0; j < 4; j++) o[i][j] = 0.f;
    float m0v = -1e30f, m1v = -1e30f, l0 = 0.f, l1 = 0.f;

    const int g = lane >> 2, q = lane & 3;
    const uint32_t a_row = (uint32_t)(w * 16 + (lane & 15)) * AP;
    const uint32_t a_k8  = ((lane >> 4) << 3) * 2;
    const int  k_row = ((lane >> 4) << 3) + (lane & 7);
    const uint32_t k_k8 = (((lane >> 3) & 1) << 3) * 2;
    const int  v_row = (((lane >> 3) & 1) << 3) + (lane & 7);
    const uint32_t v_d8 = ((lane >> 4) << 3) * 2;

    const int ntiles = 2 * qt + 2;
    for (int kti = 0; kti < ntiles; ++kti) {
        const int kv0 = kti * AKV;
        __syncthreads();
        // load K,V tiles (hi+lo): 64 x 128 each
#pragma unroll
        for (int j = 0; j < 16; j++) {
            const int arr = j >> 2;
            const int part = (j & 3) * 256 + tid;   // 0..1023
            const int r = part >> 4;
            const int c = part & 15;
            const __nv_bfloat16* gp =
                (arr == 0 ? khg : arr == 1 ? klg : arr == 2 ? vhg : vlg)
                + (size_t)(kv0 + r) * EB + c * 8;
            uint4 v = *reinterpret_cast<const uint4*>(gp);
            *reinterpret_cast<uint4*>(smem + 2 * QSZ + arr * KSZ + r * AP + c * 16) = v;
        }
        __syncthreads();

        if (kv0 > q0 + w * 16 + 15) continue;     // whole warp masked

        // ---- S = Q K^T ----
        float s[8][4];
#pragma unroll
        for (int i = 0; i < 8; i++)
#pragma unroll
            for (int j = 0; j < 4; j++) s[i][j] = 0.f;

#pragma unroll
        for (int ks = 0; ks < 8; ks++) {
            uint32_t ah[4], al[4];
            ldsm4(ah, QH + a_row + a_k8 + ks * 32);
            ldsm4(al, QL + a_row + a_k8 + ks * 32);
#pragma unroll
            for (int ntp = 0; ntp < 4; ntp++) {
                uint32_t bh[4], bl[4];
                const uint32_t ra = (uint32_t)(k_row + ntp * 16) * AP + k_k8 + ks * 32;
                ldsm4(bh, KVB + 0 * KSZ + ra);
                ldsm4(bl, KVB + 1 * KSZ + ra);
                mma16816(s[2 * ntp],     ah, bh);
                mma16816(s[2 * ntp],     ah, bl);
                mma16816(s[2 * ntp],     al, bh);
                mma16816(s[2 * ntp + 1], ah, bh + 2);
                mma16816(s[2 * ntp + 1], ah, bl + 2);
                mma16816(s[2 * ntp + 1], al, bh + 2);
            }
        }

        // ---- scale + causal mask ----
        const int r0g = q0 + w * 16 + g, r1g = r0g + 8;
        const bool needmask = (kv0 + AKV - 1) > (q0 + w * 16);
#pragma unroll
        for (int nt = 0; nt < 8; nt++) {
            const int c0 = kv0 + nt * 8 + q * 2;
            s[nt][0] *= scale; s[nt][1] *= scale; s[nt][2] *= scale; s[nt][3] *= scale;
            if (needmask) {
                if (c0     > r0g) s[nt][0] = -1e30f;
                if (c0 + 1 > r0g) s[nt][1] = -1e30f;
                if (c0     > r1g) s[nt][2] = -1e30f;
                if (c0 + 1 > r1g) s[nt][3] = -1e30f;
            }
        }

        // ---- online softmax (rows r0g, r1g) ----
        float mx0 = -1e30f, mx1 = -1e30f;
#pragma unroll
        for (int nt = 0; nt < 8; nt++) {
            mx0 = fmaxf(mx0, fmaxf(s[nt][0], s[nt][1]));
            mx1 = fmaxf(mx1, fmaxf(s[nt][2], s[nt][3]));
        }
        mx0 = fmaxf(mx0, __shfl_xor_sync(0xffffffffu, mx0, 1));
        mx0 = fmaxf(mx0, __shfl_xor_sync(0xffffffffu, mx0, 2));
        mx1 = fmaxf(mx1, __shfl_xor_sync(0xffffffffu, mx1, 1));
        mx1 = fmaxf(mx1, __shfl_xor_sync(0xffffffffu, mx1, 2));

        const float mn0 = fmaxf(m0v, mx0), mn1 = fmaxf(m1v, mx1);
        const float al0 = __expf(m0v - mn0), al1 = __expf(m1v - mn1);
        m0v = mn0; m1v = mn1;
        float rs0 = 0.f, rs1 = 0.f;
#pragma unroll
        for (int nt = 0; nt < 8; nt++) {
            s[nt][0] = __expf(s[nt][0] - mn0); rs0 += s[nt][0];
            s[nt][1] = __expf(s[nt][1] - mn0); rs0 += s[nt][1];
            s[nt][2] = __expf(s[nt][2] - mn1); rs1 += s[nt][2];
            s[nt][3] = __expf(s[nt][3] - mn1); rs1 += s[nt][3];
        }
        rs0 += __shfl_xor_sync(0xffffffffu, rs0, 1);
        rs0 += __shfl_xor_sync(0xffffffffu, rs0, 2);
        rs1 += __shfl_xor_sync(0xffffffffu, rs1, 1);
        rs1 += __shfl_xor_sync(0xffffffffu, rs1, 2);
        l0 = l0 * al0 + rs0;
        l1 = l1 * al1 + rs1;
#pragma unroll
        for (int nt = 0; nt < 16; nt++) {
            o[nt][0] *= al0; o[nt][1] *= al0; o[nt][2] *= al1; o[nt][3] *= al1;
        }

        // ---- O += P @ V ----
#pragma unroll
        for (int kt = 0; kt < 4; kt++) {
            uint32_t ph[4], pl[4];
            const float* p0 = s[2 * kt];
            const float* p1 = s[2 * kt + 1];
            ph[0] = pack_bf(p0[0], p0[1]);
            ph[1] = pack_bf(p0[2], p0[3]);
            ph[2] = pack_bf(p1[0], p1[1]);
            ph[3] = pack_bf(p1[2], p1[3]);
            pl[0] = pack_bf(p0[0] - bf_round(p0[0]), p0[1] - bf_round(p0[1]));
            pl[1] = pack_bf(p0[2] - bf_round(p0[2]), p0[3] - bf_round(p0[3]));
            pl[2] = pack_bf(p1[0] - bf_round(p1[0]), p1[1] - bf_round(p1[1]));
            pl[3] = pack_bf(p1[2] - bf_round(p1[2]), p1[3] - bf_round(p1[3]));
#pragma unroll
            for (int np = 0; np < 8; np++) {
                uint32_t bh[4], bl[4];
                const uint32_t ra = (uint32_t)(v_row + kt * 16) * AP + v_d8 + np * 32;
                ldsm4t(bh, KVB + 2 * KSZ + ra);
                ldsm4t(bl, KVB + 3 * KSZ + ra);
                mma16816(o[2 * np],     ph, bh);
                mma16816(o[2 * np],     ph, bl);
                mma16816(o[2 * np],     pl, bh);
                mma16816(o[2 * np + 1], ph, bh + 2);
                mma16816(o[2 * np + 1], ph, bl + 2);
                mma16816(o[2 * np + 1], pl, bh + 2);
            }
        }
    }

    // ---- normalize + write split-bf16 ctx ----
    const float inv0 = 1.f / l0, inv1 = 1.f / l1;
    const int r0g = q0 + w * 16 + g;
    const size_t base0 = ((size_t)b * SB + r0g) * EB + hoff;
    const size_t base1 = base0 + (size_t)8 * EB;
#pragma unroll
    for (int nt = 0; nt < 16; nt++) {
        const int c = nt * 8 + q * 2;
        const float v00 = o[nt][0] * inv0, v01 = o[nt][1] * inv0;
        const float v10 = o[nt][2] * inv1, v11 = o[nt][3] * inv1;
        const float h00 = bf_round(v00), h01 = bf_round(v01);
        const float h10 = bf_round(v10), h11 = bf_round(v11);
        *reinterpret_cast<uint32_t*>(g_ch + base0 + c) = pack_bf(v00, v01);
        *reinterpret_cast<uint32_t*>(g_cl + base0 + c) = pack_bf(v00 - h00, v01 - h01);
        *reinterpret_cast<uint32_t*>(g_ch + base1 + c) = pack_bf(v10, v11);
        *reinterpret_cast<uint32_t*>(g_cl + base1 + c) = pack_bf(v10 - h10, v11 - h11);
    }
}

// =========================================================================
extern "C" void kernel_launch(void* const* d_in, const int* in_sizes, int n_in,
                              void* d_out, int out_size)
{
    const float* x  = (const float*)d_in[0];
    const float* Wq = (const float*)d_in[1];
    const float* bq = (const float*)d_in[2];
    const float* Wk = (const float*)d_in[3];
    const float* bk = (const float*)d_in[4];
    const float* Wv = (const float*)d_in[5];
    const float* bv = (const float*)d_in[6];
    const float* Wo = (const float*)d_in[7];
    const float* bo = (const float*)d_in[8];
    float* out = (float*)d_out;

    __nv_bfloat16 *xh, *xl, *wh, *wl, *qh, *ql, *kh, *kl, *vh, *vl, *ch, *cl;
    cudaGetSymbolAddress((void**)&xh, g_xh);
    cudaGetSymbolAddress((void**)&xl, g_xl);
    cudaGetSymbolAddress((void**)&wh, g_wh);
    cudaGetSymbolAddress((void**)&wl, g_wl);
    cudaGetSymbolAddress((void**)&qh, g_qh);
    cudaGetSymbolAddress((void**)&ql, g_ql);
    cudaGetSymbolAddress((void**)&kh, g_kh);
    cudaGetSymbolAddress((void**)&kl, g_kl);
    cudaGetSymbolAddress((void**)&vh, g_vh);
    cudaGetSymbolAddress((void**)&vl, g_vl);
    cudaGetSymbolAddress((void**)&ch, g_ch);
    cudaGetSymbolAddress((void**)&cl, g_cl);

    cudaFuncSetAttribute(gemm_tc, cudaFuncAttributeMaxDynamicSharedMemorySize, GEMM_SMEM);
    cudaFuncSetAttribute(attn_tc, cudaFuncAttributeMaxDynamicSharedMemorySize, ATTN_SMEM);

    const size_t WN = (size_t)EB * EB;
    const int xn4 = (MTOT * EB) / 4;
    const int wn4 = (int)(WN / 4);

    conv_split_kernel<<<(xn4 + 255) / 256, 256>>>(x, xh, xl, xn4);
    conv_split_kernel<<<(wn4 + 255) / 256, 256>>>(Wq, wh + 0 * WN, wl + 0 * WN, wn4);
    conv_split_kernel<<<(wn4 + 255) / 256, 256>>>(Wk, wh + 1 * WN, wl + 1 * WN, wn4);
    conv_split_kernel<<<(wn4 + 255) / 256, 256>>>(Wv, wh + 2 * WN, wl + 2 * WN, wn4);
    conv_split_kernel<<<(wn4 + 255) / 256, 256>>>(Wo, wh + 3 * WN, wl + 3 * WN, wn4);

    dim3 ggrid(EB / TN, MTOT / TM);   // (16, 32)
    gemm_tc<<<ggrid, 256, GEMM_SMEM>>>(xh, xl, wh + 0 * WN, wl + 0 * WN, bq,
                                       nullptr, qh, ql, MTOT, EB, EB);
    gemm_tc<<<ggrid, 256, GEMM_SMEM>>>(xh, xl, wh + 1 * WN, wl + 1 * WN, bk,
                                       nullptr, kh, kl, MTOT, EB, EB);
    gemm_tc<<<ggrid, 256, GEMM_SMEM>>>(xh, xl, wh + 2 * WN, wl + 2 * WN, bv,
                                       nullptr, vh, vl, MTOT, EB, EB);

    attn_tc<<<dim3(SB / AQ, BB * HH), 256, ATTN_SMEM>>>();

    gemm_tc<<<ggrid, 256, GEMM_SMEM>>>(ch, cl, wh + 3 * WN, wl + 3 * WN, bo,
                                       out, nullptr, nullptr, MTOT, EB, EB);
}

// round 4
// speedup vs baseline: 3.1665x; 1.0367x over previous
#include <cuda_runtime.h>
#include <cuda_bf16.h>
#include <cstdint>
#include <cstddef>

#define EB 2048
#define SB 2048
#define BB 2
#define HH 16
#define DH 128
#define MTOT (BB*SB)

// ---------------- scratch (device globals; no allocation) ----------------
__device__ __nv_bfloat16 g_xh[(size_t)MTOT * EB];
__device__ __nv_bfloat16 g_xl[(size_t)MTOT * EB];
__device__ __nv_bfloat16 g_wh[(size_t)4 * EB * EB];
__device__ __nv_bfloat16 g_wl[(size_t)4 * EB * EB];
__device__ __nv_bfloat16 g_qh[(size_t)MTOT * EB];
__device__ __nv_bfloat16 g_ql[(size_t)MTOT * EB];
__device__ __nv_bfloat16 g_kh[(size_t)MTOT * EB];
__device__ __nv_bfloat16 g_kl[(size_t)MTOT * EB];
__device__ __nv_bfloat16 g_vh[(size_t)MTOT * EB];
__device__ __nv_bfloat16 g_vl[(size_t)MTOT * EB];
__device__ __nv_bfloat16 g_ch[(size_t)MTOT * EB];
__device__ __nv_bfloat16 g_cl[(size_t)MTOT * EB];

// ---------------- helpers ----------------
__device__ __forceinline__ uint32_t smem_u32(const void* p) {
    uint32_t a;
    asm("{ .reg .u64 t; cvta.to.shared.u64 t, %1; cvt.u32.u64 %0, t; }"
        : "=r"(a) : "l"(p));
    return a;
}

__device__ __forceinline__ void ldsm4(uint32_t* r, uint32_t a) {
    asm volatile("ldmatrix.sync.aligned.m8n8.x4.shared.b16 {%0,%1,%2,%3}, [%4];"
                 : "=r"(r[0]), "=r"(r[1]), "=r"(r[2]), "=r"(r[3]) : "r"(a));
}
__device__ __forceinline__ void ldsm4t(uint32_t* r, uint32_t a) {
    asm volatile("ldmatrix.sync.aligned.m8n8.x4.trans.shared.b16 {%0,%1,%2,%3}, [%4];"
                 : "=r"(r[0]), "=r"(r[1]), "=r"(r[2]), "=r"(r[3]) : "r"(a));
}

__device__ __forceinline__ void mma16816(float* d, const uint32_t* a, const uint32_t* b) {
    asm volatile(
        "mma.sync.aligned.m16n8k16.row.col.f32.bf16.bf16.f32 "
        "{%0,%1,%2,%3}, {%4,%5,%6,%7}, {%8,%9}, {%0,%1,%2,%3};"
        : "+f"(d[0]), "+f"(d[1]), "+f"(d[2]), "+f"(d[3])
        : "r"(a[0]), "r"(a[1]), "r"(a[2]), "r"(a[3]), "r"(b[0]), "r"(b[1]));
}

__device__ __forceinline__ void cp16(uint32_t dst, const void* src) {
    asm volatile("cp.async.cg.shared.global [%0], [%1], 16;" :: "r"(dst), "l"(src));
}
#define CP_COMMIT() asm volatile("cp.async.commit_group;" ::: "memory")
#define CP_WAIT1()  asm volatile("cp.async.wait_group 1;" ::: "memory")

__device__ __forceinline__ uint32_t pack_bf(float lo, float hi) {
    __nv_bfloat162 t = __float22bfloat162_rn(make_float2(lo, hi));
    return *reinterpret_cast<uint32_t*>(&t);
}
__device__ __forceinline__ float bf_round(float v) {
    return __bfloat162float(__float2bfloat16_rn(v));
}

// =========================================================================
// fp32 -> bf16 hi/lo split
// =========================================================================
__global__ void conv_split_kernel(const float* __restrict__ in,
                                  __nv_bfloat16* __restrict__ hi,
                                  __nv_bfloat16* __restrict__ lo, int n4)
{
    int i = blockIdx.x * blockDim.x + threadIdx.x;
    if (i >= n4) return;
    float4 v = reinterpret_cast<const float4*>(in)[i];
    float h0 = bf_round(v.x), h1 = bf_round(v.y), h2 = bf_round(v.z), h3 = bf_round(v.w);
    uint2 H, L;
    H.x = pack_bf(v.x, v.y); H.y = pack_bf(v.z, v.w);
    L.x = pack_bf(v.x - h0, v.y - h1); L.y = pack_bf(v.z - h2, v.w - h3);
    reinterpret_cast<uint2*>(hi)[i] = H;
    reinterpret_cast<uint2*>(lo)[i] = L;
}

// =========================================================================
// HMMA GEMM: C[M,N] = (Ah+Al)[M,K] @ (Bh+Bl)[N,K]^T + bias[N]
// 3-term split.  CTA 128x128, kc=32, 8 warps (2x4), warp tile 64x32.
// 2 CTAs/SM for latency hiding (regs capped at 128).
// =========================================================================
#define TM 128
#define TN 128
#define KC 32
#define GP 80                     // bytes/row in smem (64B data + 16B pad)
#define TILEB (128 * GP)          // 10240
#define STAGEB (4 * TILEB)        // 40960
#define GEMM_SMEM (2 * STAGEB)    // 81920

__device__ __forceinline__ void gemm_issue(
    const __nv_bfloat16* s0, const __nv_bfloat16* s1,
    const __nv_bfloat16* s2, const __nv_bfloat16* s3,
    int K, int k0, uint32_t base, int tid)
{
#pragma unroll
    for (int j = 0; j < 8; j++) {
        const int tile = j >> 1;
        const int part = (j & 1) * 256 + tid;   // 0..511
        const int r = part >> 2;
        const int c = part & 3;
        const __nv_bfloat16* g =
            (tile == 0 ? s0 : tile == 1 ? s1 : tile == 2 ? s2 : s3)
            + (size_t)r * K + k0 + c * 8;
        cp16(base + tile * TILEB + r * GP + c * 16, g);
    }
}

__global__ __launch_bounds__(256, 2)
void gemm_tc(const __nv_bfloat16* __restrict__ Ah, const __nv_bfloat16* __restrict__ Al,
             const __nv_bfloat16* __restrict__ Bh, const __nv_bfloat16* __restrict__ Bl,
             const float* __restrict__ bias,
             float* __restrict__ Cf,
             __nv_bfloat16* __restrict__ Ch, __nv_bfloat16* __restrict__ Cl,
             int M, int N, int K)
{
    extern __shared__ __align__(128) char smem[];
    const uint32_t sb = smem_u32(smem);
    const int tid = threadIdx.x, lane = tid & 31, wid = tid >> 5;
    const int wm = wid >> 2, wn = wid & 3;
    const int m0 = blockIdx.y * TM, n0 = blockIdx.x * TN;

    const __nv_bfloat16* s0 = Ah + (size_t)m0 * K;
    const __nv_bfloat16* s1 = Al + (size_t)m0 * K;
    const __nv_bfloat16* s2 = Bh + (size_t)n0 * K;
    const __nv_bfloat16* s3 = Bl + (size_t)n0 * K;

    gemm_issue(s0, s1, s2, s3, K, 0, sb, tid);            CP_COMMIT();
    gemm_issue(s0, s1, s2, s3, K, KC, sb + STAGEB, tid);  CP_COMMIT();

    float acc[4][4][4];
#pragma unroll
    for (int a = 0; a < 4; a++)
#pragma unroll
        for (int b = 0; b < 4; b++)
#pragma unroll
            for (int c = 0; c < 4; c++) acc[a][b][c] = 0.f;

    const int arow = wm * 64 + (lane & 15);
    const uint32_t ak8 = ((lane >> 4) << 3) * 2;
    const int brow = wn * 32 + ((lane >> 4) << 3) + (lane & 7);
    const uint32_t bk8 = (((lane >> 3) & 1) << 3) * 2;

    const int niter = K / KC;   // 64
    for (int it = 0; it < niter; ++it) {
        CP_WAIT1();
        __syncthreads();
        const uint32_t st = sb + (it & 1) * STAGEB;
        const uint32_t a_h = st, a_l = st + TILEB, b_h = st + 2 * TILEB, b_l = st + 3 * TILEB;
#pragma unroll
        for (int ks = 0; ks < 2; ++ks) {
            uint32_t ah[4][4], al[4][4];
            const uint32_t ao = ak8 + ks * 32;
#pragma unroll
            for (int mt = 0; mt < 4; mt++) {
                uint32_t ra = (uint32_t)(arow + mt * 16) * GP + ao;
                ldsm4(ah[mt], a_h + ra);
                ldsm4(al[mt], a_l + ra);
            }
#pragma unroll
            for (int np = 0; np < 2; np++) {
                uint32_t bh[4], bl[4];
                uint32_t rb = (uint32_t)(brow + np * 16) * GP + bk8 + ks * 32;
                ldsm4(bh, b_h + rb);
                ldsm4(bl, b_l + rb);
#pragma unroll
                for (int mt = 0; mt < 4; mt++) {
                    mma16816(acc[mt][2 * np],     ah[mt], bh);
                    mma16816(acc[mt][2 * np],     ah[mt], bl);
                    mma16816(acc[mt][2 * np],     al[mt], bh);
                    mma16816(acc[mt][2 * np + 1], ah[mt], bh + 2);
                    mma16816(acc[mt][2 * np + 1], ah[mt], bl + 2);
                    mma16816(acc[mt][2 * np + 1], al[mt], bh + 2);
                }
            }
        }
        __syncthreads();
        if (it + 2 < niter)
            gemm_issue(s0, s1, s2, s3, K, (it + 2) * KC, sb + (it & 1) * STAGEB, tid);
        CP_COMMIT();
    }

    // epilogue
    const int g = lane >> 2, q = lane & 3;
#pragma unroll
    for (int mt = 0; mt < 4; mt++) {
        const int r0 = m0 + wm * 64 + mt * 16 + g;
        const int r1 = r0 + 8;
#pragma unroll
        for (int nt = 0; nt < 4; nt++) {
            const int c = n0 + wn * 32 + nt * 8 + q * 2;
            const float b0 = __ldg(bias + c), b1 = __ldg(bias + c + 1);
            const float v00 = acc[mt][nt][0] + b0, v01 = acc[mt][nt][1] + b1;
            const float v10 = acc[mt][nt][2] + b0, v11 = acc[mt][nt][3] + b1;
            if (Cf) {
                *reinterpret_cast<float2*>(Cf + (size_t)r0 * N + c) = make_float2(v00, v01);
                *reinterpret_cast<float2*>(Cf + (size_t)r1 * N + c) = make_float2(v10, v11);
            } else {
                const float h00 = bf_round(v00), h01 = bf_round(v01);
                const float h10 = bf_round(v10), h11 = bf_round(v11);
                *reinterpret_cast<uint32_t*>(Ch + (size_t)r0 * N + c) = pack_bf(v00, v01);
                *reinterpret_cast<uint32_t*>(Cl + (size_t)r0 * N + c) = pack_bf(v00 - h00, v01 - h01);
                *reinterpret_cast<uint32_t*>(Ch + (size_t)r1 * N + c) = pack_bf(v10, v11);
                *reinterpret_cast<uint32_t*>(Cl + (size_t)r1 * N + c) = pack_bf(v10 - h10, v11 - h11);
            }
        }
    }
}

// =========================================================================
// Flash attention (causal) with HMMA, split-bf16, cp.async KV double-buffer.
// CTA: 128 q-rows x (b,h). 8 warps, warp owns 16 rows. KV tiles of 64.
// =========================================================================
#define AQ 128
#define AKV 64
#define AP 272                      // bytes/row (256B data + 16B pad)
#define QSZ (128 * AP)              // 34816
#define KSZ (64 * AP)               // 17408
#define AKVB (4 * KSZ)              // one KV stage: Kh,Kl,Vh,Vl = 69632
#define ATTN_SMEM (2 * QSZ + 2 * AKVB)   // 208896

__device__ __forceinline__ void attn_issue_kv(
    const __nv_bfloat16* khg, const __nv_bfloat16* klg,
    const __nv_bfloat16* vhg, const __nv_bfloat16* vlg,
    int kv0, uint32_t dst, int tid)
{
#pragma unroll
    for (int j = 0; j < 16; j++) {
        const int arr = j >> 2;
        const int part = (j & 3) * 256 + tid;   // 0..1023
        const int r = part >> 4;
        const int c = part & 15;
        const __nv_bfloat16* gp =
            (arr == 0 ? khg : arr == 1 ? klg : arr == 2 ? vhg : vlg)
            + (size_t)(kv0 + r) * EB + c * 8;
        cp16(dst + arr * KSZ + r * AP + c * 16, gp);
    }
}

__global__ __launch_bounds__(256, 1)
void attn_tc()
{
    extern __shared__ __align__(128) char smem[];
    const uint32_t sb = smem_u32(smem);
    const uint32_t QH = sb, QL = sb + QSZ, KVB = sb + 2 * QSZ;
    const int tid = threadIdx.x, lane = tid & 31, w = tid >> 5;
    const int qt = gridDim.x - 1 - blockIdx.x;      // big tiles first
    const int b  = blockIdx.y >> 4, h = blockIdx.y & 15;
    const int q0 = qt * AQ;
    const float scale = 0.08838834764831845f;       // 1/sqrt(128)

    const size_t hoff = (size_t)h * DH;
    const size_t bbase = (size_t)b * SB * EB + hoff;
    const __nv_bfloat16* qhg = g_qh + bbase + (size_t)q0 * EB;
    const __nv_bfloat16* qlg = g_ql + bbase + (size_t)q0 * EB;
    const __nv_bfloat16* khg = g_kh + bbase;
    const __nv_bfloat16* klg = g_kl + bbase;
    const __nv_bfloat16* vhg = g_vh + bbase;
    const __nv_bfloat16* vlg = g_vl + bbase;

    // prefetch KV tile 0 (stage 0)
    attn_issue_kv(khg, klg, vhg, vlg, 0, KVB, tid);
    CP_COMMIT();

    // load Q (128 x 128 bf16, hi+lo) — overlaps with the cp.async above
#pragma unroll
    for (int j = 0; j < 16; j++) {
        const int arr = j >> 3;
        const int part = (j & 7) * 256 + tid;   // 0..2047
        const int r = part >> 4;
        const int c = part & 15;
        const __nv_bfloat16* g = (arr ? qlg : qhg) + (size_t)r * EB + c * 8;
        uint4 v = *reinterpret_cast<const uint4*>(g);
        *reinterpret_cast<uint4*>(smem + arr * QSZ + r * AP + c * 16) = v;
    }

    float o[16][4];
#pragma unroll
    for (int i = 0; i < 16; i++)
#pragma unroll
        for (int j = 0; j < 4; j++) o[i][j] = 0.f;
    float m0v = -1e30f, m1v = -1e30f, l0 = 0.f, l1 = 0.f;

    const int g = lane >> 2, q = lane & 3;
    const uint32_t a_row = (uint32_t)(w * 16 + (lane & 15)) * AP;
    const uint32_t a_k8  = ((lane >> 4) << 3) * 2;
    const int  k_row = ((lane >> 4) << 3) + (lane & 7);
    const uint32_t k_k8 = (((lane >> 3) & 1) << 3) * 2;
    const int  v_row = (((lane >> 3) & 1) << 3) + (lane & 7);
    const uint32_t v_d8 = ((lane >> 4) << 3) * 2;

    const int ntiles = 2 * qt + 2;
    for (int kti = 0; kti < ntiles; ++kti) {
        const int kv0 = kti * AKV;
        __syncthreads();   // all readers done with the stage we write next
        if (kti + 1 < ntiles)
            attn_issue_kv(khg, klg, vhg, vlg, (kti + 1) * AKV,
                          KVB + ((kti + 1) & 1) * AKVB, tid);
        CP_COMMIT();       // always commit (keeps FIFO bookkeeping exact)
        CP_WAIT1();        // tile kti complete
        __syncthreads();

        if (kv0 > q0 + w * 16 + 15) continue;     // whole warp masked

        const uint32_t ST = KVB + (kti & 1) * AKVB;

        // ---- S = Q K^T ----
        float s[8][4];
#pragma unroll
        for (int i = 0; i < 8; i++)
#pragma unroll
            for (int j = 0; j < 4; j++) s[i][j] = 0.f;

#pragma unroll
        for (int ks = 0; ks < 8; ks++) {
            uint32_t ah[4], al[4];
            ldsm4(ah, QH + a_row + a_k8 + ks * 32);
            ldsm4(al, QL + a_row + a_k8 + ks * 32);
#pragma unroll
            for (int ntp = 0; ntp < 4; ntp++) {
                uint32_t bh[4], bl[4];
                const uint32_t ra = (uint32_t)(k_row + ntp * 16) * AP + k_k8 + ks * 32;
                ldsm4(bh, ST + 0 * KSZ + ra);
                ldsm4(bl, ST + 1 * KSZ + ra);
                mma16816(s[2 * ntp],     ah, bh);
                mma16816(s[2 * ntp],     ah, bl);
                mma16816(s[2 * ntp],     al, bh);
                mma16816(s[2 * ntp + 1], ah, bh + 2);
                mma16816(s[2 * ntp + 1], ah, bl + 2);
                mma16816(s[2 * ntp + 1], al, bh + 2);
            }
        }

        // ---- scale + causal mask ----
        const int r0g = q0 + w * 16 + g, r1g = r0g + 8;
        const bool needmask = (kv0 + AKV - 1) > (q0 + w * 16);
#pragma unroll
        for (int nt = 0; nt < 8; nt++) {
            const int c0 = kv0 + nt * 8 + q * 2;
            s[nt][0] *= scale; s[nt][1] *= scale; s[nt][2] *= scale; s[nt][3] *= scale;
            if (needmask) {
                if (c0     > r0g) s[nt][0] = -1e30f;
                if (c0 + 1 > r0g) s[nt][1] = -1e30f;
                if (c0     > r1g) s[nt][2] = -1e30f;
                if (c0 + 1 > r1g) s[nt][3] = -1e30f;
            }
        }

        // ---- online softmax (rows r0g, r1g) ----
        float mx0 = -1e30f, mx1 = -1e30f;
#pragma unroll
        for (int nt = 0; nt < 8; nt++) {
            mx0 = fmaxf(mx0, fmaxf(s[nt][0], s[nt][1]));
            mx1 = fmaxf(mx1, fmaxf(s[nt][2], s[nt][3]));
        }
        mx0 = fmaxf(mx0, __shfl_xor_sync(0xffffffffu, mx0, 1));
        mx0 = fmaxf(mx0, __shfl_xor_sync(0xffffffffu, mx0, 2));
        mx1 = fmaxf(mx1, __shfl_xor_sync(0xffffffffu, mx1, 1));
        mx1 = fmaxf(mx1, __shfl_xor_sync(0xffffffffu, mx1, 2));

        const float mn0 = fmaxf(m0v, mx0), mn1 = fmaxf(m1v, mx1);
        const float al0 = __expf(m0v - mn0), al1 = __expf(m1v - mn1);
        m0v = mn0; m1v = mn1;
        float rs0 = 0.f, rs1 = 0.f;
#pragma unroll
        for (int nt = 0; nt < 8; nt++) {
            s[nt][0] = __expf(s[nt][0] - mn0); rs0 += s[nt][0];
            s[nt][1] = __expf(s[nt][1] - mn0); rs0 += s[nt][1];
            s[nt][2] = __expf(s[nt][2] - mn1); rs1 += s[nt][2];
            s[nt][3] = __expf(s[nt][3] - mn1); rs1 += s[nt][3];
        }
        rs0 += __shfl_xor_sync(0xffffffffu, rs0, 1);
        rs0 += __shfl_xor_sync(0xffffffffu, rs0, 2);
        rs1 += __shfl_xor_sync(0xffffffffu, rs1, 1);
        rs1 += __shfl_xor_sync(0xffffffffu, rs1, 2);
        l0 = l0 * al0 + rs0;
        l1 = l1 * al1 + rs1;
#pragma unroll
        for (int nt = 0; nt < 16; nt++) {
            o[nt][0] *= al0; o[nt][1] *= al0; o[nt][2] *= al1; o[nt][3] *= al1;
        }

        // ---- O += P @ V ----
#pragma unroll
        for (int kt = 0; kt < 4; kt++) {
            uint32_t ph[4], pl[4];
            const float* p0 = s[2 * kt];
            const float* p1 = s[2 * kt + 1];
            ph[0] = pack_bf(p0[0], p0[1]);
            ph[1] = pack_bf(p0[2], p0[3]);
            ph[2] = pack_bf(p1[0], p1[1]);
            ph[3] = pack_bf(p1[2], p1[3]);
            pl[0] = pack_bf(p0[0] - bf_round(p0[0]), p0[1] - bf_round(p0[1]));
            pl[1] = pack_bf(p0[2] - bf_round(p0[2]), p0[3] - bf_round(p0[3]));
            pl[2] = pack_bf(p1[0] - bf_round(p1[0]), p1[1] - bf_round(p1[1]));
            pl[3] = pack_bf(p1[2] - bf_round(p1[2]), p1[3] - bf_round(p1[3]));
#pragma unroll
            for (int np = 0; np < 8; np++) {
                uint32_t bh[4], bl[4];
                const uint32_t ra = (uint32_t)(v_row + kt * 16) * AP + v_d8 + np * 32;
                ldsm4t(bh, ST + 2 * KSZ + ra);
                ldsm4t(bl, ST + 3 * KSZ + ra);
                mma16816(o[2 * np],     ph, bh);
                mma16816(o[2 * np],     ph, bl);
                mma16816(o[2 * np],     pl, bh);
                mma16816(o[2 * np + 1], ph, bh + 2);
                mma16816(o[2 * np + 1], ph, bl + 2);
                mma16816(o[2 * np + 1], pl, bh + 2);
            }
        }
    }

    // ---- normalize + write split-bf16 ctx ----
    const float inv0 = 1.f / l0, inv1 = 1.f / l1;
    const int r0g = q0 + w * 16 + g;
    const size_t base0 = ((size_t)b * SB + r0g) * EB + hoff;
    const size_t base1 = base0 + (size_t)8 * EB;
#pragma unroll
    for (int nt = 0; nt < 16; nt++) {
        const int c = nt * 8 + q * 2;
        const float v00 = o[nt][0] * inv0, v01 = o[nt][1] * inv0;
        const float v10 = o[nt][2] * inv1, v11 = o[nt][3] * inv1;
        const float h00 = bf_round(v00), h01 = bf_round(v01);
        const float h10 = bf_round(v10), h11 = bf_round(v11);
        *reinterpret_cast<uint32_t*>(g_ch + base0 + c) = pack_bf(v00, v01);
        *reinterpret_cast<uint32_t*>(g_cl + base0 + c) = pack_bf(v00 - h00, v01 - h01);
        *reinterpret_cast<uint32_t*>(g_ch + base1 + c) = pack_bf(v10, v11);
        *reinterpret_cast<uint32_t*>(g_cl + base1 + c) = pack_bf(v10 - h10, v11 - h11);
    }
}

// =========================================================================
extern "C" void kernel_launch(void* const* d_in, const int* in_sizes, int n_in,
                              void* d_out, int out_size)
{
    const float* x  = (const float*)d_in[0];
    const float* Wq = (const float*)d_in[1];
    const float* bq = (const float*)d_in[2];
    const float* Wk = (const float*)d_in[3];
    const float* bk = (const float*)d_in[4];
    const float* Wv = (const float*)d_in[5];
    const float* bv = (const float*)d_in[6];
    const float* Wo = (const float*)d_in[7];
    const float* bo = (const float*)d_in[8];
    float* out = (float*)d_out;

    __nv_bfloat16 *xh, *xl, *wh, *wl, *qh, *ql, *kh, *kl, *vh, *vl, *ch, *cl;
    cudaGetSymbolAddress((void**)&xh, g_xh);
    cudaGetSymbolAddress((void**)&xl, g_xl);
    cudaGetSymbolAddress((void**)&wh, g_wh);
    cudaGetSymbolAddress((void**)&wl, g_wl);
    cudaGetSymbolAddress((void**)&qh, g_qh);
    cudaGetSymbolAddress((void**)&ql, g_ql);
    cudaGetSymbolAddress((void**)&kh, g_kh);
    cudaGetSymbolAddress((void**)&kl, g_kl);
    cudaGetSymbolAddress((void**)&vh, g_vh);
    cudaGetSymbolAddress((void**)&vl, g_vl);
    cudaGetSymbolAddress((void**)&ch, g_ch);
    cudaGetSymbolAddress((void**)&cl, g_cl);

    cudaFuncSetAttribute(gemm_tc, cudaFuncAttributeMaxDynamicSharedMemorySize, GEMM_SMEM);
    cudaFuncSetAttribute(attn_tc, cudaFuncAttributeMaxDynamicSharedMemorySize, ATTN_SMEM);

    const size_t WN = (size_t)EB * EB;
    const int xn4 = (MTOT * EB) / 4;
    const int wn4 = (int)(WN / 4);

    conv_split_kernel<<<(xn4 + 255) / 256, 256>>>(x, xh, xl, xn4);
    conv_split_kernel<<<(wn4 + 255) / 256, 256>>>(Wq, wh + 0 * WN, wl + 0 * WN, wn4);
    conv_split_kernel<<<(wn4 + 255) / 256, 256>>>(Wk, wh + 1 * WN, wl + 1 * WN, wn4);
    conv_split_kernel<<<(wn4 + 255) / 256, 256>>>(Wv, wh + 2 * WN, wl + 2 * WN, wn4);
    conv_split_kernel<<<(wn4 + 255) / 256, 256>>>(Wo, wh + 3 * WN, wl + 3 * WN, wn4);

    dim3 ggrid(EB / TN, MTOT / TM);   // (16, 32)
    gemm_tc<<<ggrid, 256, GEMM_SMEM>>>(xh, xl, wh + 0 * WN, wl + 0 * WN, bq,
                                       nullptr, qh, ql, MTOT, EB, EB);
    gemm_tc<<<ggrid, 256, GEMM_SMEM>>>(xh, xl, wh + 1 * WN, wl + 1 * WN, bk,
                                       nullptr, kh, kl, MTOT, EB, EB);
    gemm_tc<<<ggrid, 256, GEMM_SMEM>>>(xh, xl, wh + 2 * WN, wl + 2 * WN, bv,
                                       nullptr, vh, vl, MTOT, EB, EB);

    attn_tc<<<dim3(SB / AQ, BB * HH), 256, ATTN_SMEM>>>();

    gemm_tc<<<ggrid, 256, GEMM_SMEM>>>(ch, cl, wh + 3 * WN, wl + 3 * WN, bo,
                                       out, nullptr, nullptr, MTOT, EB, EB);
}